// round 14
// baseline (speedup 1.0000x reference)
#include <cuda_runtime.h>
#include <cuda_bf16.h>
#include <cstdint>
#include <cstddef>

#define SEQ   2048
#define DIM   1024
#define NHEAD 16
#define NK    64
#define HDIM  64
#define NA4   (SEQ * DIM / 4)
#define NB4   (DIM * DIM / 4)

// ---------------------------------------------------------------------------
// Device-global scratch (no allocations allowed)
// ---------------------------------------------------------------------------
__device__ float g_h[SEQ * DIM];
__device__ int   g_routes32[SEQ * NK];
__device__ int   g_is64;
__device__ __nv_bfloat16 g_Ahi[SEQ * DIM];   // A hi (x, then attn output)
__device__ __nv_bfloat16 g_Alo[SEQ * DIM];   // A lo
__device__ __nv_bfloat16 g_Bhi[DIM * DIM];   // W_in hi
__device__ __nv_bfloat16 g_Blo[DIM * DIM];   // W_in lo
__device__ __nv_bfloat16 g_Whi[DIM * DIM];   // W_out hi
__device__ __nv_bfloat16 g_Wlo[DIM * DIM];   // W_out lo

// ---------------------------------------------------------------------------
// PTX helpers (sm_80-era features only — harness targets plain sm_103)
// ---------------------------------------------------------------------------
__device__ __forceinline__ uint32_t smem_u32(const void* p) {
    uint32_t a;
    asm("{ .reg .u64 t; cvta.to.shared.u64 t, %1; cvt.u32.u64 %0, t; }"
        : "=r"(a) : "l"(p));
    return a;
}

__device__ __forceinline__ void cp_async16(uint32_t dst, const void* src) {
    asm volatile("cp.async.cg.shared.global [%0], [%1], 16;"
                 :: "r"(dst), "l"(src) : "memory");
}

__device__ __forceinline__ void ldsm_x4(uint32_t* r, uint32_t addr) {
    asm volatile("ldmatrix.sync.aligned.m8n8.x4.shared.b16 {%0,%1,%2,%3}, [%4];"
                 : "=r"(r[0]), "=r"(r[1]), "=r"(r[2]), "=r"(r[3]) : "r"(addr));
}
__device__ __forceinline__ void ldsm_x2(uint32_t* r, uint32_t addr) {
    asm volatile("ldmatrix.sync.aligned.m8n8.x2.shared.b16 {%0,%1}, [%2];"
                 : "=r"(r[0]), "=r"(r[1]) : "r"(addr));
}

__device__ __forceinline__ void mma_bf16(float* d, const uint32_t* a, const uint32_t* b) {
    asm volatile(
        "mma.sync.aligned.m16n8k16.row.col.f32.bf16.bf16.f32 "
        "{%0,%1,%2,%3}, {%4,%5,%6,%7}, {%8,%9}, {%0,%1,%2,%3};"
        : "+f"(d[0]), "+f"(d[1]), "+f"(d[2]), "+f"(d[3])
        : "r"(a[0]), "r"(a[1]), "r"(a[2]), "r"(a[3]), "r"(b[0]), "r"(b[1]));
}

// ---------------------------------------------------------------------------
// Routes dtype normalization (proven in Round 3)
// ---------------------------------------------------------------------------
__global__ void detect_routes_kernel(const unsigned int* __restrict__ w)
{
    __shared__ int nonzero;
    if (threadIdx.x == 0) nonzero = 0;
    __syncthreads();
    for (int i = 2 * threadIdx.x + 1; i < SEQ * NK; i += 2 * blockDim.x)
        if (w[i] != 0u) { nonzero = 1; break; }
    __syncthreads();
    if (threadIdx.x == 0) g_is64 = (nonzero == 0) ? 1 : 0;
}

__global__ void convert_routes_kernel(const void* __restrict__ r)
{
    int i = blockIdx.x * blockDim.x + threadIdx.x;
    if (i >= SEQ * NK) return;
    int v;
    if (g_is64) v = (int)((const long long*)r)[i];
    else        v = ((const int*)r)[i];
    v = v < 0 ? 0 : (v >= SEQ ? SEQ - 1 : v);
    g_routes32[i] = v;
}

// ---------------------------------------------------------------------------
// Mega-split: x, W_in, W_out -> bf16 hi/lo in ONE launch.
// ---------------------------------------------------------------------------
__global__ void split3_kernel(const float* __restrict__ x,
                              const float* __restrict__ Wi,
                              const float* __restrict__ Wo)
{
    int i = blockIdx.x * blockDim.x + threadIdx.x;
    const float* src;
    __nv_bfloat16 *hi, *lo;
    if (i < NA4)            {            src = x;  hi = g_Ahi; lo = g_Alo; }
    else if (i < NA4 + NB4) { i -= NA4;  src = Wi; hi = g_Bhi; lo = g_Blo; }
    else                    { i -= NA4 + NB4; src = Wo; hi = g_Whi; lo = g_Wlo; }

    float4 f = ((const float4*)src)[i];
    __nv_bfloat16 h0 = __float2bfloat16(f.x), h1 = __float2bfloat16(f.y);
    __nv_bfloat16 h2 = __float2bfloat16(f.z), h3 = __float2bfloat16(f.w);
    hi[i*4+0] = h0; hi[i*4+1] = h1; hi[i*4+2] = h2; hi[i*4+3] = h3;
    lo[i*4+0] = __float2bfloat16(f.x - __bfloat162float(h0));
    lo[i*4+1] = __float2bfloat16(f.y - __bfloat162float(h1));
    lo[i*4+2] = __float2bfloat16(f.z - __bfloat162float(h2));
    lo[i*4+3] = __float2bfloat16(f.w - __bfloat162float(h3));
}

// ---------------------------------------------------------------------------
// mma.sync bf16-split GEMM: C[M,N] = A[M,K] @ B[N,K]^T  (+bias+resid if EPI)
// D ~= Ahi@Bhi^T + Ahi@Blo^T + Alo@Bhi^T   (fp32 accumulate)
// CTA tile 128x64 (M x N), BK=32, 8 warps (4 x 2) each computing 32x32.
// Grid 256 CTAs, 2 CTAs/SM resident -> single full wave on 148 SMs.
// ---------------------------------------------------------------------------
#define BK      32
#define NCHUNK  (DIM / BK)          // 32
#define PITCH   40                  // halves per smem row (32 data + 8 pad)
#define A_TILE  (128 * PITCH * 2)   // 10240 B
#define B_TILE  (64  * PITCH * 2)   // 5120 B
#define STAGE   (2 * A_TILE + 2 * B_TILE)   // 30720 B
#define GSMEM   (2 * STAGE)                 // 61440 B

template<bool EPI>
__global__ __launch_bounds__(256, 2)
void mma_gemm(const __nv_bfloat16* __restrict__ Ahi, const __nv_bfloat16* __restrict__ Alo,
              const __nv_bfloat16* __restrict__ Bhi, const __nv_bfloat16* __restrict__ Blo,
              float* __restrict__ C, const float* __restrict__ bias,
              const float* __restrict__ resid)
{
    extern __shared__ char smem[];
    const uint32_t sbase = smem_u32(smem);
    const int tid    = threadIdx.x;
    const int lane   = tid & 31;
    const int wid    = tid >> 5;
    const int warp_m = wid & 3;     // 4 warps over M -> 32 rows each
    const int warp_n = wid >> 2;    // 2 warps over N -> 32 cols each
    const int rm     = blockIdx.y * 128;
    const int cn     = blockIdx.x * 64;

    const char* Ahib = (const char*)(Ahi + (size_t)rm * DIM);
    const char* Alob = (const char*)(Alo + (size_t)rm * DIM);
    const char* Bhib = (const char*)(Bhi + (size_t)cn * DIM);
    const char* Blob = (const char*)(Blo + (size_t)cn * DIM);

    // 1536 16B-segments per stage (Ahi 512, Alo 512, Bhi 256, Blo 256);
    // 256 threads x 6 iterations, warp-uniform roles.
    auto load_stage = [&](int c, int s) {
        uint32_t dbase = sbase + (uint32_t)s * STAGE;
        #pragma unroll
        for (int j = 0; j < 6; j++) {
            int e = tid + j * 256;
            uint32_t doff; const char* src;
            if (e < 1024) {                       // A tiles
                int tl  = e >> 9;                 // 0:hi 1:lo
                int idx = e & 511;
                int row = idx >> 2, kseg = idx & 3;
                doff = dbase + (uint32_t)tl * A_TILE
                     + (uint32_t)(row * (PITCH * 2) + kseg * 16);
                src  = (tl ? Alob : Ahib)
                     + (size_t)row * (DIM * 2) + c * (BK * 2) + kseg * 16;
            } else {                              // B tiles
                int tl  = (e >> 8) & 1;           // 0:hi 1:lo
                int idx = e & 255;
                int row = idx >> 2, kseg = idx & 3;
                doff = dbase + 2u * A_TILE + (uint32_t)tl * B_TILE
                     + (uint32_t)(row * (PITCH * 2) + kseg * 16);
                src  = (tl ? Blob : Bhib)
                     + (size_t)row * (DIM * 2) + c * (BK * 2) + kseg * 16;
            }
            cp_async16(doff, src);
        }
        asm volatile("cp.async.commit_group;" ::: "memory");
    };

    float acc[2][4][4];
    #pragma unroll
    for (int mt = 0; mt < 2; mt++)
        #pragma unroll
        for (int nt = 0; nt < 4; nt++)
            #pragma unroll
            for (int i = 0; i < 4; i++) acc[mt][nt][i] = 0.f;

    load_stage(0, 0);
    load_stage(1, 1);

    const int arow  = warp_m * 32 + (lane & 15);
    const int acol8 = (lane >> 4) * 8;            // halves
    const int bl    = lane & 15;
    const int brow  = warp_n * 32 + (bl & 7);
    const int bcol8 = (bl >> 3) * 8;              // halves

    for (int c = 0; c < NCHUNK; c++) {
        const int s = c & 1;
        if (c == NCHUNK - 1) asm volatile("cp.async.wait_group 0;" ::: "memory");
        else                 asm volatile("cp.async.wait_group 1;" ::: "memory");
        __syncthreads();

        const uint32_t sa_hi = sbase + (uint32_t)s * STAGE;
        const uint32_t sa_lo = sa_hi + A_TILE;
        const uint32_t sb_hi = sa_hi + 2 * A_TILE;
        const uint32_t sb_lo = sb_hi + B_TILE;

        #pragma unroll
        for (int ks = 0; ks < 2; ks++) {
            const int kb = ks * 16;               // halves
            uint32_t afh[2][4], afl[2][4];
            #pragma unroll
            for (int mt = 0; mt < 2; mt++) {
                uint32_t off = (uint32_t)((arow + mt * 16) * (PITCH * 2) + (kb + acol8) * 2);
                ldsm_x4(afh[mt], sa_hi + off);
                ldsm_x4(afl[mt], sa_lo + off);
            }
            uint32_t bfh[4][2], bfl[4][2];
            #pragma unroll
            for (int nt = 0; nt < 4; nt++) {
                uint32_t off = (uint32_t)((brow + nt * 8) * (PITCH * 2) + (kb + bcol8) * 2);
                ldsm_x2(bfh[nt], sb_hi + off);
                ldsm_x2(bfl[nt], sb_lo + off);
            }
            #pragma unroll
            for (int mt = 0; mt < 2; mt++)
                #pragma unroll
                for (int nt = 0; nt < 4; nt++) {
                    mma_bf16(acc[mt][nt], afh[mt], bfh[nt]);
                    mma_bf16(acc[mt][nt], afh[mt], bfl[nt]);
                    mma_bf16(acc[mt][nt], afl[mt], bfh[nt]);
                }
        }
        __syncthreads();
        if (c + 2 < NCHUNK) load_stage(c + 2, s);
    }

    // ---- epilogue: direct register -> global stores ----
    #pragma unroll
    for (int mt = 0; mt < 2; mt++) {
        const int r0 = rm + warp_m * 32 + mt * 16 + (lane >> 2);
        #pragma unroll
        for (int nt = 0; nt < 4; nt++) {
            const int col = cn + warp_n * 32 + nt * 8 + (lane & 3) * 2;
            float2 v0 = make_float2(acc[mt][nt][0], acc[mt][nt][1]);
            float2 v1 = make_float2(acc[mt][nt][2], acc[mt][nt][3]);
            if (EPI) {
                float2 bb = *(const float2*)(bias + col);
                float2 ra = *(const float2*)(resid + (size_t)r0 * DIM + col);
                float2 rb = *(const float2*)(resid + (size_t)(r0 + 8) * DIM + col);
                v0.x += bb.x + ra.x; v0.y += bb.y + ra.y;
                v1.x += bb.x + rb.x; v1.y += bb.y + rb.y;
            }
            *(float2*)(C + (size_t)r0 * DIM + col)       = v0;
            *(float2*)(C + (size_t)(r0 + 8) * DIM + col) = v1;
        }
    }
}

// ---------------------------------------------------------------------------
// Gather-attention (hot loop unchanged). Epilogue writes the bf16 hi/lo split
// of the fused output directly into GEMM2's A buffers.
// ---------------------------------------------------------------------------
__global__ __launch_bounds__(512, 2)
void attn_kernel(const float* __restrict__ hbuf,
                 const int* __restrict__ routes,
                 __nv_bfloat16* __restrict__ ohi,
                 __nv_bfloat16* __restrict__ olo)
{
    __shared__ int sr[NK];
    const int s    = blockIdx.x;
    const int tid  = threadIdx.x;
    const int warp = tid >> 5;
    const int lane = tid & 31;
    if (tid < NK) sr[tid] = routes[s * NK + tid];
    __syncthreads();

    const int off = warp * HDIM + lane * 2;
    const float2 q = *(const float2*)(hbuf + (size_t)s * DIM + off);

    float m = -1e30f, l = 0.f, a0 = 0.f, a1 = 0.f;

    #pragma unroll 1
    for (int c = 0; c < NK; c += 8) {
        float2 v[8];
        #pragma unroll
        for (int k = 0; k < 8; k++)
            v[k] = *(const float2*)(hbuf + (size_t)sr[c + k] * DIM + off);

        float p[8];
        #pragma unroll
        for (int k = 0; k < 8; k++) {
            float tacc = q.x * v[k].x + q.y * v[k].y;
            #pragma unroll
            for (int o = 16; o > 0; o >>= 1)
                tacc += __shfl_xor_sync(0xffffffffu, tacc, o);
            p[k] = tacc * 0.125f;
        }

        float cmax = p[0];
        #pragma unroll
        for (int k = 1; k < 8; k++) cmax = fmaxf(cmax, p[k]);
        float mnew = fmaxf(m, cmax);
        float f = __expf(m - mnew);
        float e[8], psum = 0.f;
        #pragma unroll
        for (int k = 0; k < 8; k++) { e[k] = __expf(p[k] - mnew); psum += e[k]; }
        l = l * f + psum;
        a0 *= f; a1 *= f;
        m = mnew;
        #pragma unroll
        for (int k = 0; k < 8; k++) {
            a0 = fmaf(e[k], v[k].x, a0);
            a1 = fmaf(e[k], v[k].y, a1);
        }
    }

    const float inv = 1.f / l;
    const float f0 = a0 * inv, f1 = a1 * inv;
    const __nv_bfloat16 h0 = __float2bfloat16(f0);
    const __nv_bfloat16 h1 = __float2bfloat16(f1);
    __nv_bfloat162 hv, lv;
    hv.x = h0; hv.y = h1;
    lv.x = __float2bfloat16(f0 - __bfloat162float(h0));
    lv.y = __float2bfloat16(f1 - __bfloat162float(h1));
    *(__nv_bfloat162*)(ohi + (size_t)s * DIM + off) = hv;
    *(__nv_bfloat162*)(olo + (size_t)s * DIM + off) = lv;
}

// ---------------------------------------------------------------------------
// Launch sequence
// ---------------------------------------------------------------------------
extern "C" void kernel_launch(void* const* d_in, const int* in_sizes, int n_in,
                              void* d_out, int out_size)
{
    const float* x      = (const float*)d_in[0];
    const void*  routes = d_in[1];
    const float* W_in   = (const float*)d_in[2];
    const float* W_out  = (const float*)d_in[3];
    const float* b_out  = (const float*)d_in[4];
    float*       out    = (float*)d_out;

    float* hbuf; int* rbuf;
    __nv_bfloat16 *ahi, *alo, *bhi, *blo, *whi, *wlo;
    cudaGetSymbolAddress((void**)&hbuf, g_h);
    cudaGetSymbolAddress((void**)&rbuf, g_routes32);
    cudaGetSymbolAddress((void**)&ahi,  g_Ahi);
    cudaGetSymbolAddress((void**)&alo,  g_Alo);
    cudaGetSymbolAddress((void**)&bhi,  g_Bhi);
    cudaGetSymbolAddress((void**)&blo,  g_Blo);
    cudaGetSymbolAddress((void**)&whi,  g_Whi);
    cudaGetSymbolAddress((void**)&wlo,  g_Wlo);

    static bool attr_set = false;
    if (!attr_set) {
        cudaFuncSetAttribute(mma_gemm<false>, cudaFuncAttributeMaxDynamicSharedMemorySize, GSMEM);
        cudaFuncSetAttribute(mma_gemm<true>,  cudaFuncAttributeMaxDynamicSharedMemorySize, GSMEM);
        attr_set = true;
    }

    detect_routes_kernel<<<1, 256>>>((const unsigned int*)routes);
    convert_routes_kernel<<<(SEQ * NK + 255) / 256, 256>>>(routes);

    // one launch splits x, W_in, W_out
    split3_kernel<<<(NA4 + 2 * NB4) / 256, 256>>>(x, W_in, W_out);

    dim3 gblk(256);
    dim3 ggrd(DIM / 64, SEQ / 128);  // (16, 16) = 256 CTAs -> one full wave

    // GEMM1: h = x @ W_in^T
    mma_gemm<false><<<ggrd, gblk, GSMEM>>>(ahi, alo, bhi, blo, hbuf, nullptr, nullptr);

    // attention: writes bf16 hi/lo of fused directly into A buffers
    attn_kernel<<<SEQ, 512>>>(hbuf, rbuf, ahi, alo);

    // GEMM2: out = fused @ W_out^T + b_out + x
    mma_gemm<true><<<ggrd, gblk, GSMEM>>>(ahi, alo, whi, wlo, out, b_out, x);
}

// round 16
// speedup vs baseline: 1.0348x; 1.0348x over previous
#include <cuda_runtime.h>
#include <cuda_bf16.h>
#include <cstdint>
#include <cstddef>

#define SEQ   2048
#define DIM   1024
#define NHEAD 16
#define NK    64
#define HDIM  64
#define NA4   (SEQ * DIM / 4)
#define NB4   (DIM * DIM / 4)

// ---------------------------------------------------------------------------
// Device-global scratch (no allocations allowed)
// ---------------------------------------------------------------------------
__device__ float g_h[SEQ * DIM];
__device__ int   g_routes32[SEQ * NK];
__device__ int   g_is64;
__device__ __nv_bfloat16 g_Ahi[SEQ * DIM];   // A hi (x, then attn output)
__device__ __nv_bfloat16 g_Alo[SEQ * DIM];   // A lo
__device__ __nv_bfloat16 g_Bhi[DIM * DIM];   // W_in hi
__device__ __nv_bfloat16 g_Blo[DIM * DIM];   // W_in lo
__device__ __nv_bfloat16 g_Whi[DIM * DIM];   // W_out hi
__device__ __nv_bfloat16 g_Wlo[DIM * DIM];   // W_out lo

// ---------------------------------------------------------------------------
// PTX helpers (sm_80-era features only — harness targets plain sm_103)
// ---------------------------------------------------------------------------
__device__ __forceinline__ uint32_t smem_u32(const void* p) {
    uint32_t a;
    asm("{ .reg .u64 t; cvta.to.shared.u64 t, %1; cvt.u32.u64 %0, t; }"
        : "=r"(a) : "l"(p));
    return a;
}

__device__ __forceinline__ void cp_async16(uint32_t dst, const void* src) {
    asm volatile("cp.async.cg.shared.global [%0], [%1], 16;"
                 :: "r"(dst), "l"(src) : "memory");
}

__device__ __forceinline__ void ldsm_x4(uint32_t* r, uint32_t addr) {
    asm volatile("ldmatrix.sync.aligned.m8n8.x4.shared.b16 {%0,%1,%2,%3}, [%4];"
                 : "=r"(r[0]), "=r"(r[1]), "=r"(r[2]), "=r"(r[3]) : "r"(addr));
}
__device__ __forceinline__ void ldsm_x2(uint32_t* r, uint32_t addr) {
    asm volatile("ldmatrix.sync.aligned.m8n8.x2.shared.b16 {%0,%1}, [%2];"
                 : "=r"(r[0]), "=r"(r[1]) : "r"(addr));
}

__device__ __forceinline__ void mma_bf16(float* d, const uint32_t* a, const uint32_t* b) {
    asm volatile(
        "mma.sync.aligned.m16n8k16.row.col.f32.bf16.bf16.f32 "
        "{%0,%1,%2,%3}, {%4,%5,%6,%7}, {%8,%9}, {%0,%1,%2,%3};"
        : "+f"(d[0]), "+f"(d[1]), "+f"(d[2]), "+f"(d[3])
        : "r"(a[0]), "r"(a[1]), "r"(a[2]), "r"(a[3]), "r"(b[0]), "r"(b[1]));
}

// ---------------------------------------------------------------------------
// Routes dtype normalization (proven in Round 3)
// ---------------------------------------------------------------------------
__global__ void detect_routes_kernel(const unsigned int* __restrict__ w)
{
    __shared__ int nonzero;
    if (threadIdx.x == 0) nonzero = 0;
    __syncthreads();
    for (int i = 2 * threadIdx.x + 1; i < SEQ * NK; i += 2 * blockDim.x)
        if (w[i] != 0u) { nonzero = 1; break; }
    __syncthreads();
    if (threadIdx.x == 0) g_is64 = (nonzero == 0) ? 1 : 0;
}

__global__ void convert_routes_kernel(const void* __restrict__ r)
{
    int i = blockIdx.x * blockDim.x + threadIdx.x;
    if (i >= SEQ * NK) return;
    int v;
    if (g_is64) v = (int)((const long long*)r)[i];
    else        v = ((const int*)r)[i];
    v = v < 0 ? 0 : (v >= SEQ ? SEQ - 1 : v);
    g_routes32[i] = v;
}

// ---------------------------------------------------------------------------
// Mega-split: x, W_in, W_out -> bf16 hi/lo in ONE launch.
// ---------------------------------------------------------------------------
__global__ void split3_kernel(const float* __restrict__ x,
                              const float* __restrict__ Wi,
                              const float* __restrict__ Wo)
{
    int i = blockIdx.x * blockDim.x + threadIdx.x;
    const float* src;
    __nv_bfloat16 *hi, *lo;
    if (i < NA4)            {            src = x;  hi = g_Ahi; lo = g_Alo; }
    else if (i < NA4 + NB4) { i -= NA4;  src = Wi; hi = g_Bhi; lo = g_Blo; }
    else                    { i -= NA4 + NB4; src = Wo; hi = g_Whi; lo = g_Wlo; }

    float4 f = ((const float4*)src)[i];
    __nv_bfloat16 h0 = __float2bfloat16(f.x), h1 = __float2bfloat16(f.y);
    __nv_bfloat16 h2 = __float2bfloat16(f.z), h3 = __float2bfloat16(f.w);
    hi[i*4+0] = h0; hi[i*4+1] = h1; hi[i*4+2] = h2; hi[i*4+3] = h3;
    lo[i*4+0] = __float2bfloat16(f.x - __bfloat162float(h0));
    lo[i*4+1] = __float2bfloat16(f.y - __bfloat162float(h1));
    lo[i*4+2] = __float2bfloat16(f.z - __bfloat162float(h2));
    lo[i*4+3] = __float2bfloat16(f.w - __bfloat162float(h3));
}

// ---------------------------------------------------------------------------
// mma.sync bf16-split GEMM: C[M,N] = A[M,K] @ B[N,K]^T  (+bias+resid if EPI)
// D ~= Ahi@Bhi^T + Ahi@Blo^T + Alo@Bhi^T   (fp32 accumulate)
// CTA tile 128x128 (the proven 180us geometry), BK=32, 8 warps (4x2), each
// computing 32x64. NEW vs 180us base: the 3 split-products are issued as
// three nt-sweeps (all AhiBhi, then all AhiBlo, then all AloBhi) so 8
// independent HMMAs separate successive writes to any accumulator — breaks
// the acc RAW chain. Per-accumulator product ORDER is unchanged -> result
// is bit-identical.
// ---------------------------------------------------------------------------
#define BK      32
#define NCHUNK  (DIM / BK)          // 32
#define PITCH   40                  // halves per smem row (32 data + 8 pad)
#define TILEH   (128 * PITCH * 2)   // bytes per tile (10240)
#define STAGE   (4 * TILEH)         // Ahi,Alo,Bhi,Blo (40960)
#define GSMEM   (2 * STAGE)         // 81920

template<bool EPI>
__global__ __launch_bounds__(256, 1)
void mma_gemm(const __nv_bfloat16* __restrict__ Ahi, const __nv_bfloat16* __restrict__ Alo,
              const __nv_bfloat16* __restrict__ Bhi, const __nv_bfloat16* __restrict__ Blo,
              float* __restrict__ C, const float* __restrict__ bias,
              const float* __restrict__ resid)
{
    extern __shared__ char smem[];
    const uint32_t sbase = smem_u32(smem);
    const int tid    = threadIdx.x;
    const int lane   = tid & 31;
    const int wid    = tid >> 5;
    const int warp_m = wid & 3;
    const int warp_n = wid >> 2;
    const int rm     = blockIdx.y * 128;
    const int cn     = blockIdx.x * 128;

    const int t    = tid >> 6;      // 0:Ahi 1:Alo 2:Bhi 3:Blo
    const int tsub = tid & 63;
    const char* tsrc;
    if      (t == 0) tsrc = (const char*)(Ahi + (size_t)rm * DIM);
    else if (t == 1) tsrc = (const char*)(Alo + (size_t)rm * DIM);
    else if (t == 2) tsrc = (const char*)(Bhi + (size_t)cn * DIM);
    else             tsrc = (const char*)(Blo + (size_t)cn * DIM);

    auto load_stage = [&](int c, int s) {
        uint32_t dbase = sbase + (uint32_t)s * STAGE + (uint32_t)t * TILEH;
        #pragma unroll
        for (int j = 0; j < 8; j++) {
            int seg  = tsub + j * 64;
            int row  = seg >> 2;
            int kseg = seg & 3;
            cp_async16(dbase + (uint32_t)(row * (PITCH * 2) + kseg * 16),
                       tsrc + (size_t)row * (DIM * 2) + c * (BK * 2) + kseg * 16);
        }
        asm volatile("cp.async.commit_group;" ::: "memory");
    };

    float acc[2][8][4];
    #pragma unroll
    for (int mt = 0; mt < 2; mt++)
        #pragma unroll
        for (int nt = 0; nt < 8; nt++)
            #pragma unroll
            for (int i = 0; i < 4; i++) acc[mt][nt][i] = 0.f;

    load_stage(0, 0);
    load_stage(1, 1);

    const int arow  = warp_m * 32 + (lane & 15);
    const int acol8 = (lane >> 4) * 8;
    const int bl    = lane & 15;
    const int brow  = warp_n * 64 + (bl & 7);
    const int bcol8 = (bl >> 3) * 8;

    for (int c = 0; c < NCHUNK; c++) {
        const int s = c & 1;
        if (c == NCHUNK - 1) asm volatile("cp.async.wait_group 0;" ::: "memory");
        else                 asm volatile("cp.async.wait_group 1;" ::: "memory");
        __syncthreads();

        const uint32_t sa_hi = sbase + (uint32_t)s * STAGE;
        const uint32_t sa_lo = sa_hi + TILEH;
        const uint32_t sb_hi = sa_hi + 2 * TILEH;
        const uint32_t sb_lo = sa_hi + 3 * TILEH;

        #pragma unroll
        for (int ks = 0; ks < 2; ks++) {
            const int kb = ks * 16;
            uint32_t afh[2][4], afl[2][4];
            #pragma unroll
            for (int mt = 0; mt < 2; mt++) {
                uint32_t off = (uint32_t)((arow + mt * 16) * (PITCH * 2) + (kb + acol8) * 2);
                ldsm_x4(afh[mt], sa_hi + off);
                ldsm_x4(afl[mt], sa_lo + off);
            }
            uint32_t bfh[8][2], bfl[8][2];
            #pragma unroll
            for (int nt = 0; nt < 8; nt++) {
                uint32_t off = (uint32_t)((brow + nt * 8) * (PITCH * 2) + (kb + bcol8) * 2);
                ldsm_x2(bfh[nt], sb_hi + off);
                ldsm_x2(bfl[nt], sb_lo + off);
            }
            // Interleaved product sweeps: 8 independent HMMAs between
            // successive updates of the same accumulator. Per-acc order is
            // still hi*hi, hi*lo, lo*hi -> bit-identical result.
            #pragma unroll
            for (int mt = 0; mt < 2; mt++) {
                #pragma unroll
                for (int nt = 0; nt < 8; nt++)
                    mma_bf16(acc[mt][nt], afh[mt], bfh[nt]);
                #pragma unroll
                for (int nt = 0; nt < 8; nt++)
                    mma_bf16(acc[mt][nt], afh[mt], bfl[nt]);
                #pragma unroll
                for (int nt = 0; nt < 8; nt++)
                    mma_bf16(acc[mt][nt], afl[mt], bfh[nt]);
            }
        }
        __syncthreads();
        if (c + 2 < NCHUNK) load_stage(c + 2, s);
    }

    #pragma unroll
    for (int mt = 0; mt < 2; mt++) {
        const int r0 = rm + warp_m * 32 + mt * 16 + (lane >> 2);
        #pragma unroll
        for (int nt = 0; nt < 8; nt++) {
            const int col = cn + warp_n * 64 + nt * 8 + (lane & 3) * 2;
            float2 v0 = make_float2(acc[mt][nt][0], acc[mt][nt][1]);
            float2 v1 = make_float2(acc[mt][nt][2], acc[mt][nt][3]);
            if (EPI) {
                float2 bb = *(const float2*)(bias + col);
                float2 ra = *(const float2*)(resid + (size_t)r0 * DIM + col);
                float2 rb = *(const float2*)(resid + (size_t)(r0 + 8) * DIM + col);
                v0.x += bb.x + ra.x; v0.y += bb.y + ra.y;
                v1.x += bb.x + rb.x; v1.y += bb.y + rb.y;
            }
            *(float2*)(C + (size_t)r0 * DIM + col)       = v0;
            *(float2*)(C + (size_t)(r0 + 8) * DIM + col) = v1;
        }
    }
}

// ---------------------------------------------------------------------------
// Gather-attention (hot loop unchanged). Epilogue writes the bf16 hi/lo split
// of the fused output directly into GEMM2's A buffers.
// ---------------------------------------------------------------------------
__global__ __launch_bounds__(512, 2)
void attn_kernel(const float* __restrict__ hbuf,
                 const int* __restrict__ routes,
                 __nv_bfloat16* __restrict__ ohi,
                 __nv_bfloat16* __restrict__ olo)
{
    __shared__ int sr[NK];
    const int s    = blockIdx.x;
    const int tid  = threadIdx.x;
    const int warp = tid >> 5;
    const int lane = tid & 31;
    if (tid < NK) sr[tid] = routes[s * NK + tid];
    __syncthreads();

    const int off = warp * HDIM + lane * 2;
    const float2 q = *(const float2*)(hbuf + (size_t)s * DIM + off);

    float m = -1e30f, l = 0.f, a0 = 0.f, a1 = 0.f;

    #pragma unroll 1
    for (int c = 0; c < NK; c += 8) {
        float2 v[8];
        #pragma unroll
        for (int k = 0; k < 8; k++)
            v[k] = *(const float2*)(hbuf + (size_t)sr[c + k] * DIM + off);

        float p[8];
        #pragma unroll
        for (int k = 0; k < 8; k++) {
            float tacc = q.x * v[k].x + q.y * v[k].y;
            #pragma unroll
            for (int o = 16; o > 0; o >>= 1)
                tacc += __shfl_xor_sync(0xffffffffu, tacc, o);
            p[k] = tacc * 0.125f;
        }

        float cmax = p[0];
        #pragma unroll
        for (int k = 1; k < 8; k++) cmax = fmaxf(cmax, p[k]);
        float mnew = fmaxf(m, cmax);
        float f = __expf(m - mnew);
        float e[8], psum = 0.f;
        #pragma unroll
        for (int k = 0; k < 8; k++) { e[k] = __expf(p[k] - mnew); psum += e[k]; }
        l = l * f + psum;
        a0 *= f; a1 *= f;
        m = mnew;
        #pragma unroll
        for (int k = 0; k < 8; k++) {
            a0 = fmaf(e[k], v[k].x, a0);
            a1 = fmaf(e[k], v[k].y, a1);
        }
    }

    const float inv = 1.f / l;
    const float f0 = a0 * inv, f1 = a1 * inv;
    const __nv_bfloat16 h0 = __float2bfloat16(f0);
    const __nv_bfloat16 h1 = __float2bfloat16(f1);
    __nv_bfloat162 hv, lv;
    hv.x = h0; hv.y = h1;
    lv.x = __float2bfloat16(f0 - __bfloat162float(h0));
    lv.y = __float2bfloat16(f1 - __bfloat162float(h1));
    *(__nv_bfloat162*)(ohi + (size_t)s * DIM + off) = hv;
    *(__nv_bfloat162*)(olo + (size_t)s * DIM + off) = lv;
}

// ---------------------------------------------------------------------------
// Launch sequence
// ---------------------------------------------------------------------------
extern "C" void kernel_launch(void* const* d_in, const int* in_sizes, int n_in,
                              void* d_out, int out_size)
{
    const float* x      = (const float*)d_in[0];
    const void*  routes = d_in[1];
    const float* W_in   = (const float*)d_in[2];
    const float* W_out  = (const float*)d_in[3];
    const float* b_out  = (const float*)d_in[4];
    float*       out    = (float*)d_out;

    float* hbuf; int* rbuf;
    __nv_bfloat16 *ahi, *alo, *bhi, *blo, *whi, *wlo;
    cudaGetSymbolAddress((void**)&hbuf, g_h);
    cudaGetSymbolAddress((void**)&rbuf, g_routes32);
    cudaGetSymbolAddress((void**)&ahi,  g_Ahi);
    cudaGetSymbolAddress((void**)&alo,  g_Alo);
    cudaGetSymbolAddress((void**)&bhi,  g_Bhi);
    cudaGetSymbolAddress((void**)&blo,  g_Blo);
    cudaGetSymbolAddress((void**)&whi,  g_Whi);
    cudaGetSymbolAddress((void**)&wlo,  g_Wlo);

    static bool attr_set = false;
    if (!attr_set) {
        cudaFuncSetAttribute(mma_gemm<false>, cudaFuncAttributeMaxDynamicSharedMemorySize, GSMEM);
        cudaFuncSetAttribute(mma_gemm<true>,  cudaFuncAttributeMaxDynamicSharedMemorySize, GSMEM);
        attr_set = true;
    }

    detect_routes_kernel<<<1, 256>>>((const unsigned int*)routes);
    convert_routes_kernel<<<(SEQ * NK + 255) / 256, 256>>>(routes);

    // one launch splits x, W_in, W_out
    split3_kernel<<<(NA4 + 2 * NB4) / 256, 256>>>(x, W_in, W_out);

    dim3 gblk(256);
    dim3 ggrd(DIM / 128, SEQ / 128); // (8, 16)

    // GEMM1: h = x @ W_in^T
    mma_gemm<false><<<ggrd, gblk, GSMEM>>>(ahi, alo, bhi, blo, hbuf, nullptr, nullptr);

    // attention: writes bf16 hi/lo of fused directly into A buffers
    attn_kernel<<<SEQ, 512>>>(hbuf, rbuf, ahi, alo);

    // GEMM2: out = fused @ W_out^T + b_out + x
    mma_gemm<true><<<ggrd, gblk, GSMEM>>>(ahi, alo, whi, wlo, out, b_out, x);
}

// round 17
// speedup vs baseline: 1.5123x; 1.4615x over previous
#include <cuda_runtime.h>
#include <cuda_fp16.h>
#include <cstdint>
#include <cstddef>

#define SEQ   2048
#define DIM   1024
#define NHEAD 16
#define NK    64
#define HDIM  64
#define NA4   (SEQ * DIM / 4)
#define NB4   (DIM * DIM / 4)

// ---------------------------------------------------------------------------
// Device-global scratch (no allocations allowed)
// ---------------------------------------------------------------------------
__device__ float  g_h[SEQ * DIM];
__device__ int    g_routes32[SEQ * NK];
__device__ int    g_is64;
__device__ __half g_A16[SEQ * DIM];   // A (x, then attn output) fp16
__device__ __half g_B16[DIM * DIM];   // W_in  fp16
__device__ __half g_W16[DIM * DIM];   // W_out fp16

// ---------------------------------------------------------------------------
// PTX helpers (sm_80-era features only — harness targets plain sm_103)
// ---------------------------------------------------------------------------
__device__ __forceinline__ uint32_t smem_u32(const void* p) {
    uint32_t a;
    asm("{ .reg .u64 t; cvta.to.shared.u64 t, %1; cvt.u32.u64 %0, t; }"
        : "=r"(a) : "l"(p));
    return a;
}

__device__ __forceinline__ void cp_async16(uint32_t dst, const void* src) {
    asm volatile("cp.async.cg.shared.global [%0], [%1], 16;"
                 :: "r"(dst), "l"(src) : "memory");
}

__device__ __forceinline__ void ldsm_x4(uint32_t* r, uint32_t addr) {
    asm volatile("ldmatrix.sync.aligned.m8n8.x4.shared.b16 {%0,%1,%2,%3}, [%4];"
                 : "=r"(r[0]), "=r"(r[1]), "=r"(r[2]), "=r"(r[3]) : "r"(addr));
}
__device__ __forceinline__ void ldsm_x2(uint32_t* r, uint32_t addr) {
    asm volatile("ldmatrix.sync.aligned.m8n8.x2.shared.b16 {%0,%1}, [%2];"
                 : "=r"(r[0]), "=r"(r[1]) : "r"(addr));
}

// fp16 inputs, fp32 accumulate
__device__ __forceinline__ void mma_f16(float* d, const uint32_t* a, const uint32_t* b) {
    asm volatile(
        "mma.sync.aligned.m16n8k16.row.col.f32.f16.f16.f32 "
        "{%0,%1,%2,%3}, {%4,%5,%6,%7}, {%8,%9}, {%0,%1,%2,%3};"
        : "+f"(d[0]), "+f"(d[1]), "+f"(d[2]), "+f"(d[3])
        : "r"(a[0]), "r"(a[1]), "r"(a[2]), "r"(a[3]), "r"(b[0]), "r"(b[1]));
}

// ---------------------------------------------------------------------------
// Routes dtype normalization (proven in Round 3)
// ---------------------------------------------------------------------------
__global__ void detect_routes_kernel(const unsigned int* __restrict__ w)
{
    __shared__ int nonzero;
    if (threadIdx.x == 0) nonzero = 0;
    __syncthreads();
    for (int i = 2 * threadIdx.x + 1; i < SEQ * NK; i += 2 * blockDim.x)
        if (w[i] != 0u) { nonzero = 1; break; }
    __syncthreads();
    if (threadIdx.x == 0) g_is64 = (nonzero == 0) ? 1 : 0;
}

__global__ void convert_routes_kernel(const void* __restrict__ r)
{
    int i = blockIdx.x * blockDim.x + threadIdx.x;
    if (i >= SEQ * NK) return;
    int v;
    if (g_is64) v = (int)((const long long*)r)[i];
    else        v = ((const int*)r)[i];
    v = v < 0 ? 0 : (v >= SEQ ? SEQ - 1 : v);
    g_routes32[i] = v;
}

// ---------------------------------------------------------------------------
// Convert x, W_in, W_out -> fp16 in ONE launch.
// ---------------------------------------------------------------------------
__global__ void cvt3_kernel(const float* __restrict__ x,
                            const float* __restrict__ Wi,
                            const float* __restrict__ Wo)
{
    int i = blockIdx.x * blockDim.x + threadIdx.x;
    const float* src;
    __half* dst;
    if (i < NA4)            {            src = x;  dst = g_A16; }
    else if (i < NA4 + NB4) { i -= NA4;  src = Wi; dst = g_B16; }
    else                    { i -= NA4 + NB4; src = Wo; dst = g_W16; }

    float4 f = ((const float4*)src)[i];
    __half2 h01 = __floats2half2_rn(f.x, f.y);
    __half2 h23 = __floats2half2_rn(f.z, f.w);
    *(__half2*)(dst + (size_t)i * 4)     = h01;
    *(__half2*)(dst + (size_t)i * 4 + 2) = h23;
}

// ---------------------------------------------------------------------------
// mma.sync fp16 single-product GEMM: C[M,N] = A[M,K] @ B[N,K]^T (+bias+resid)
// CTA tile 128x128 (proven geometry), BK=32, 8 warps (4x2) each 32x64.
// fp16 inputs, fp32 accumulate. 1/3 the MMA count of the bf16-split version.
// ---------------------------------------------------------------------------
#define BK      32
#define NCHUNK  (DIM / BK)          // 32
#define PITCH   40                  // halves per smem row (32 data + 8 pad)
#define TILEH   (128 * PITCH * 2)   // bytes per tile (10240)
#define STAGE   (2 * TILEH)         // A,B (20480)
#define GSMEM   (2 * STAGE)         // 40960

template<bool EPI>
__global__ __launch_bounds__(256, 1)
void mma_gemm(const __half* __restrict__ A16, const __half* __restrict__ B16,
              float* __restrict__ C, const float* __restrict__ bias,
              const float* __restrict__ resid)
{
    extern __shared__ char smem[];
    const uint32_t sbase = smem_u32(smem);
    const int tid    = threadIdx.x;
    const int lane   = tid & 31;
    const int wid    = tid >> 5;
    const int warp_m = wid & 3;
    const int warp_n = wid >> 2;
    const int rm     = blockIdx.y * 128;
    const int cn     = blockIdx.x * 128;

    // 2 tiles x 512 16B-segments; 128 threads/tile, 4 iterations each
    const int t    = tid >> 7;      // 0:A 1:B
    const int tsub = tid & 127;
    const char* tsrc = (t == 0) ? (const char*)(A16 + (size_t)rm * DIM)
                                : (const char*)(B16 + (size_t)cn * DIM);

    auto load_stage = [&](int c, int s) {
        uint32_t dbase = sbase + (uint32_t)s * STAGE + (uint32_t)t * TILEH;
        #pragma unroll
        for (int j = 0; j < 4; j++) {
            int seg  = tsub + j * 128;    // 0..511
            int row  = seg >> 2;
            int kseg = seg & 3;
            cp_async16(dbase + (uint32_t)(row * (PITCH * 2) + kseg * 16),
                       tsrc + (size_t)row * (DIM * 2) + c * (BK * 2) + kseg * 16);
        }
        asm volatile("cp.async.commit_group;" ::: "memory");
    };

    float acc[2][8][4];
    #pragma unroll
    for (int mt = 0; mt < 2; mt++)
        #pragma unroll
        for (int nt = 0; nt < 8; nt++)
            #pragma unroll
            for (int i = 0; i < 4; i++) acc[mt][nt][i] = 0.f;

    load_stage(0, 0);
    load_stage(1, 1);

    const int arow  = warp_m * 32 + (lane & 15);
    const int acol8 = (lane >> 4) * 8;
    const int bl    = lane & 15;
    const int brow  = warp_n * 64 + (bl & 7);
    const int bcol8 = (bl >> 3) * 8;

    for (int c = 0; c < NCHUNK; c++) {
        const int s = c & 1;
        if (c == NCHUNK - 1) asm volatile("cp.async.wait_group 0;" ::: "memory");
        else                 asm volatile("cp.async.wait_group 1;" ::: "memory");
        __syncthreads();

        const uint32_t sa = sbase + (uint32_t)s * STAGE;
        const uint32_t sb = sa + TILEH;

        #pragma unroll
        for (int ks = 0; ks < 2; ks++) {
            const int kb = ks * 16;
            uint32_t af[2][4];
            #pragma unroll
            for (int mt = 0; mt < 2; mt++) {
                uint32_t off = (uint32_t)((arow + mt * 16) * (PITCH * 2) + (kb + acol8) * 2);
                ldsm_x4(af[mt], sa + off);
            }
            uint32_t bf[8][2];
            #pragma unroll
            for (int nt = 0; nt < 8; nt++) {
                uint32_t off = (uint32_t)((brow + nt * 8) * (PITCH * 2) + (kb + bcol8) * 2);
                ldsm_x2(bf[nt], sb + off);
            }
            #pragma unroll
            for (int mt = 0; mt < 2; mt++)
                #pragma unroll
                for (int nt = 0; nt < 8; nt++)
                    mma_f16(acc[mt][nt], af[mt], bf[nt]);
        }
        __syncthreads();
        if (c + 2 < NCHUNK) load_stage(c + 2, s);
    }

    #pragma unroll
    for (int mt = 0; mt < 2; mt++) {
        const int r0 = rm + warp_m * 32 + mt * 16 + (lane >> 2);
        #pragma unroll
        for (int nt = 0; nt < 8; nt++) {
            const int col = cn + warp_n * 64 + nt * 8 + (lane & 3) * 2;
            float2 v0 = make_float2(acc[mt][nt][0], acc[mt][nt][1]);
            float2 v1 = make_float2(acc[mt][nt][2], acc[mt][nt][3]);
            if (EPI) {
                float2 bb = *(const float2*)(bias + col);
                float2 ra = *(const float2*)(resid + (size_t)r0 * DIM + col);
                float2 rb = *(const float2*)(resid + (size_t)(r0 + 8) * DIM + col);
                v0.x += bb.x + ra.x; v0.y += bb.y + ra.y;
                v1.x += bb.x + rb.x; v1.y += bb.y + rb.y;
            }
            *(float2*)(C + (size_t)r0 * DIM + col)       = v0;
            *(float2*)(C + (size_t)(r0 + 8) * DIM + col) = v1;
        }
    }
}

// ---------------------------------------------------------------------------
// Gather-attention (hot loop unchanged from proven rounds). Epilogue writes
// fp16 fused output directly into GEMM2's A buffer.
// ---------------------------------------------------------------------------
__global__ __launch_bounds__(512, 2)
void attn_kernel(const float* __restrict__ hbuf,
                 const int* __restrict__ routes,
                 __half* __restrict__ o16)
{
    __shared__ int sr[NK];
    const int s    = blockIdx.x;
    const int tid  = threadIdx.x;
    const int warp = tid >> 5;
    const int lane = tid & 31;
    if (tid < NK) sr[tid] = routes[s * NK + tid];
    __syncthreads();

    const int off = warp * HDIM + lane * 2;
    const float2 q = *(const float2*)(hbuf + (size_t)s * DIM + off);

    float m = -1e30f, l = 0.f, a0 = 0.f, a1 = 0.f;

    #pragma unroll 1
    for (int c = 0; c < NK; c += 8) {
        float2 v[8];
        #pragma unroll
        for (int k = 0; k < 8; k++)
            v[k] = *(const float2*)(hbuf + (size_t)sr[c + k] * DIM + off);

        float p[8];
        #pragma unroll
        for (int k = 0; k < 8; k++) {
            float tacc = q.x * v[k].x + q.y * v[k].y;
            #pragma unroll
            for (int o = 16; o > 0; o >>= 1)
                tacc += __shfl_xor_sync(0xffffffffu, tacc, o);
            p[k] = tacc * 0.125f;
        }

        float cmax = p[0];
        #pragma unroll
        for (int k = 1; k < 8; k++) cmax = fmaxf(cmax, p[k]);
        float mnew = fmaxf(m, cmax);
        float f = __expf(m - mnew);
        float e[8], psum = 0.f;
        #pragma unroll
        for (int k = 0; k < 8; k++) { e[k] = __expf(p[k] - mnew); psum += e[k]; }
        l = l * f + psum;
        a0 *= f; a1 *= f;
        m = mnew;
        #pragma unroll
        for (int k = 0; k < 8; k++) {
            a0 = fmaf(e[k], v[k].x, a0);
            a1 = fmaf(e[k], v[k].y, a1);
        }
    }

    const float inv = 1.f / l;
    __half2 hv = __floats2half2_rn(a0 * inv, a1 * inv);
    *(__half2*)(o16 + (size_t)s * DIM + off) = hv;
}

// ---------------------------------------------------------------------------
// Launch sequence
// ---------------------------------------------------------------------------
extern "C" void kernel_launch(void* const* d_in, const int* in_sizes, int n_in,
                              void* d_out, int out_size)
{
    const float* x      = (const float*)d_in[0];
    const void*  routes = d_in[1];
    const float* W_in   = (const float*)d_in[2];
    const float* W_out  = (const float*)d_in[3];
    const float* b_out  = (const float*)d_in[4];
    float*       out    = (float*)d_out;

    float* hbuf; int* rbuf;
    __half *a16, *b16, *w16;
    cudaGetSymbolAddress((void**)&hbuf, g_h);
    cudaGetSymbolAddress((void**)&rbuf, g_routes32);
    cudaGetSymbolAddress((void**)&a16,  g_A16);
    cudaGetSymbolAddress((void**)&b16,  g_B16);
    cudaGetSymbolAddress((void**)&w16,  g_W16);

    static bool attr_set = false;
    if (!attr_set) {
        cudaFuncSetAttribute(mma_gemm<false>, cudaFuncAttributeMaxDynamicSharedMemorySize, GSMEM);
        cudaFuncSetAttribute(mma_gemm<true>,  cudaFuncAttributeMaxDynamicSharedMemorySize, GSMEM);
        attr_set = true;
    }

    detect_routes_kernel<<<1, 256>>>((const unsigned int*)routes);
    convert_routes_kernel<<<(SEQ * NK + 255) / 256, 256>>>(routes);

    // one launch converts x, W_in, W_out to fp16
    cvt3_kernel<<<(NA4 + 2 * NB4) / 256, 256>>>(x, W_in, W_out);

    dim3 gblk(256);
    dim3 ggrd(DIM / 128, SEQ / 128); // (8, 16)

    // GEMM1: h = x @ W_in^T
    mma_gemm<false><<<ggrd, gblk, GSMEM>>>(a16, b16, hbuf, nullptr, nullptr);

    // attention: writes fp16 fused directly into GEMM2's A buffer
    attn_kernel<<<SEQ, 512>>>(hbuf, rbuf, a16);

    // GEMM2: out = fused @ W_out^T + b_out + x
    mma_gemm<true><<<ggrd, gblk, GSMEM>>>(a16, w16, out, b_out, x);
}